// round 16
// baseline (speedup 1.0000x reference)
#include <cuda_runtime.h>
#include <cstdint>

// Problem constants (fixed by the dataset: B=1, P=8192, N=16384, C=64)
#define GRID_DIM 10
#define NCELLS   (GRID_DIM * GRID_DIM * GRID_DIM)
#define NPTS_MAX 16384
#define NQ_MAX   8192
#define CFEAT    64
#define OUTC     115          // 64 fcd + 3 xyz + 24 sin + 24 cos
#define KNN      10
#define R2F      0.01f
#define RADIUSF  0.1f
#define CANDMAX  128          // per-query candidate cap (E ~ 68.6, sigma ~ 8.3)
#define WPB      8            // warps (queries) per block: share one cell's neighborhood
#define BTHR     256          // build threads per block
#define UINF     0xFFFFFFFFu

// ---- scratch: static __device__ arrays (no allocation allowed) ----
__device__ int    g_cntH[2][NCELLS];         // point histogram, ping-pong by parity
__device__ int    g_cntS[2][NCELLS];         // point scatter counters, ping-pong
__device__ int    g_qcntH[2][NCELLS];        // query histogram, ping-pong
__device__ int    g_qcntS[2][NCELLS];        // query scatter counters, ping-pong
__device__ int    g_entry;                   // monotonic across replays
__device__ int    g_done;                    // monotonic across replays
__device__ int    g_cell_start[NCELLS + 1];
__device__ float4 g_sorted[NPTS_MAX + 96];   // {x,y,z,|p|^2}; +96 zero pad
__device__ int    g_sidx[NPTS_MAX];          // original point index
__device__ int    g_qorder[NQ_MAX];          // queries sorted by cell

__device__ __forceinline__ int cell_coord(float v) {
    int c = (int)(v * 10.0f);
    return c < 0 ? 0 : (c > 9 ? 9 : c);
}
__device__ __forceinline__ int cell_of(float x, float y, float z) {
    return (cell_coord(z) * GRID_DIM + cell_coord(y)) * GRID_DIM + cell_coord(x);
}

// 256-thread exclusive scan of cnt[0..NCELLS) into s_out; returns nothing.
// (4 cells per thread + shfl warp-scan hierarchy; caller syncs.)
__device__ __forceinline__ void scan1000(const int* __restrict__ cnt,
                                         int* __restrict__ s_out,
                                         int* __restrict__ warp_sums,
                                         int t) {
    const int lane = t & 31, wid = t >> 5;
    const int c0 = t * 4;
    int loc[4], pref = 0;
    #pragma unroll
    for (int r = 0; r < 4; r++) {
        int cc = c0 + r;
        int v = (cc < NCELLS) ? cnt[cc] : 0;
        loc[r] = pref; pref += v;
    }
    int inc = pref;
    #pragma unroll
    for (int off = 1; off < 32; off <<= 1) {
        int o = __shfl_up_sync(0xffffffffu, inc, off);
        if (lane >= off) inc += o;
    }
    if (lane == 31) warp_sums[wid] = inc;
    __syncthreads();
    if (wid == 0) {
        int v = (lane < BTHR / 32) ? warp_sums[lane] : 0;
        int s = v;
        #pragma unroll
        for (int off = 1; off < BTHR / 32; off <<= 1) {
            int o = __shfl_up_sync(0xffffffffu, s, off);
            if (lane >= off) s += o;
        }
        if (lane < BTHR / 32) warp_sums[lane] = s - v;
    }
    __syncthreads();
    const int base = warp_sums[wid] + (inc - pref);
    #pragma unroll
    for (int r = 0; r < 4; r++) {
        int cc = c0 + r;
        if (cc < NCELLS) s_out[cc] = base + loc[r];
    }
    if (t == BTHR - 1) s_out[NCELLS] = base + pref;   // total
}

// ---- build: count pts+queries -> poll-all -> 2x scan -> scatter both ----
__global__ void __launch_bounds__(BTHR)
build_kernel(const float* __restrict__ pcd, const float* __restrict__ xyz,
             int N, int P) {
    __shared__ int s_start[NCELLS + 1];
    __shared__ int s_qstart[NCELLS + 1];
    __shared__ int warp_sums[BTHR / 32];
    __shared__ int s_epoch;

    const int t   = threadIdx.x;
    const int bid = blockIdx.x;
    const int nb  = gridDim.x;
    const int i   = bid * BTHR + t;

    if (t == 0) s_epoch = atomicAdd(&g_entry, 1) / nb;
    __syncthreads();
    const int E = s_epoch;
    const int p = E & 1;

    // ---- count points ----
    float x = 0.f, y = 0.f, z = 0.f, pp = 0.f;
    int c = 0;
    const bool valid = (i < N);
    if (valid) {
        x = pcd[3 * i]; y = pcd[3 * i + 1]; z = pcd[3 * i + 2];
        pp = __fadd_rn(__fadd_rn(__fmul_rn(x, x), __fmul_rn(y, y)),
                       __fmul_rn(z, z));            // |p|^2 as reference
        c = cell_of(x, y, z);
        atomicAdd(&g_cntH[p][c], 1);
    }
    // ---- count queries ----
    int qc = 0;
    const bool qvalid = (i < P);
    if (qvalid) {
        float qx = xyz[3 * i], qy = xyz[3 * i + 1], qz = xyz[3 * i + 2];
        qc = cell_of(qx, qy, qz);
        atomicAdd(&g_qcntH[p][qc], 1);
    }
    __threadfence();
    __syncthreads();
    if (t == 0) {
        atomicAdd(&g_done, 1);
        while (*((volatile int*)&g_done) < (E + 1) * nb) __nanosleep(32);
    }
    __syncthreads();
    __threadfence();

    // ---- redundant parallel scans into smem (identical in every block) ----
    scan1000(g_cntH[p], s_start, warp_sums, t);
    __syncthreads();
    scan1000(g_qcntH[p], s_qstart, warp_sums, t);
    __syncthreads();

    // ---- each block writes its 16-entry slice of g_cell_start[0..1000] ----
    if (t < 16) {
        int cc = bid * 16 + t;
        if (cc <= NCELLS) g_cell_start[cc] = s_start[cc];
    }

    // ---- scatter points ----
    if (valid) {
        int pos = s_start[c] + atomicAdd(&g_cntS[p][c], 1);
        g_sorted[pos] = make_float4(x, y, z, pp);
        g_sidx[pos] = i;
    }
    // ---- scatter queries (cell-sorted order for knn locality) ----
    if (qvalid) {
        int pos = s_qstart[qc] + atomicAdd(&g_qcntS[p][qc], 1);
        g_qorder[pos] = i;
    }

    // ---- zero the other parity for the next epoch ----
    if (i < NCELLS) {
        g_cntH[1 - p][i] = 0;
        g_cntS[1 - p][i] = 0;
        g_qcntH[1 - p][i] = 0;
        g_qcntS[1 - p][i] = 0;
    }
}

// compare-exchange on (d2,pos) pairs, ascending
#define CE_(da,pa,db,pb) { \
    bool sw_ = (da > db) || ((da == db) && (pa > pb)); \
    unsigned td_ = sw_ ? db : da, tp_ = sw_ ? pb : pa; \
    db = sw_ ? da : db; pb = sw_ ? pa : pb; da = td_; pa = tp_; }

// ---- main: warp-per-query radius KNN + aggregate + positional encoding ----
__global__ void __launch_bounds__(WPB * 32)
knn_kernel(const float* __restrict__ xyz,
           const float* __restrict__ feat,
           float* __restrict__ out, int P) {
    __shared__ uint2 buf[WPB][CANDMAX + 1];    // +1: slot 128 is the trash slot

    const int w    = threadIdx.x >> 5;
    const int lane = threadIdx.x & 31;
    const int gid  = blockIdx.x * WPB + w;
    if (gid >= P) return;                  // warp-uniform
    const int q = g_qorder[gid];           // cell-sorted query order

    const float qx = xyz[3 * q], qy = xyz[3 * q + 1], qz = xyz[3 * q + 2];
    const float qq = __fadd_rn(__fadd_rn(__fmul_rn(qx, qx), __fmul_rn(qy, qy)),
                               __fmul_rn(qz, qz));

    const int iy = cell_coord(qy), iz = cell_coord(qz);
    const int y0 = max(iy - 1, 0), y1 = min(iy + 1, GRID_DIM - 1);
    const int z0 = max(iz - 1, 0), z1 = min(iz + 1, GRID_DIM - 1);

    // hoisted per-axis cell-interval distances (3 each)
    float dz2v[3], dy2v[3];
    #pragma unroll
    for (int r = 0; r < 3; r++) {
        int zz = iz - 1 + r;
        float dz = fmaxf(0.0f, fmaxf(0.1f * zz - qz, qz - 0.1f * (zz + 1)));
        dz2v[r] = dz * dz;
        int yy = iy - 1 + r;
        float dy = fmaxf(0.0f, fmaxf(0.1f * yy - qy, qy - 0.1f * (yy + 1)));
        dy2v[r] = dy * dy;
    }

    int count = 0;                          // warp-uniform candidate count
    const unsigned lmask = (1u << lane) - 1u;
    for (int zz = z0; zz <= z1; zz++) {
        const float dz2 = dz2v[zz - (iz - 1)];
        for (int yy = y0; yy <= y1; yy++) {
            float rowd2 = dy2v[yy - (iy - 1)] + dz2;
            if (rowd2 > R2F + 1e-6f) continue;
            float s = fmaxf(R2F + 1e-7f - rowd2, 1e-12f);
            float rx = s * __frsqrt_rn(s) * 1.0002f + 1e-6f;   // >= sqrt(s)
            int xa = cell_coord(qx - rx);
            int xb = cell_coord(qx + rx);
            const int cbase = (zz * GRID_DIM + yy) * GRID_DIM;
            const int segS = g_cell_start[cbase + xa];
            const int segE = g_cell_start[cbase + xb + 1];
            // 64 points per iteration: 2 per lane, 2 independent LDG.128s.
            // Stores are BRANCHLESS: failing/overflow lanes write trash slot.
            for (int j0 = segS; j0 < segE; j0 += 64) {
                const int ja = j0 + lane;
                const int jb = ja + 32;
                float4 pa = g_sorted[ja];   // padded array: always safe
                float4 pb = g_sorted[jb];
                float dota = fmaf(qz, pa.z, fmaf(qy, pa.y, __fmul_rn(qx, pa.x)));
                float d2a  = __fsub_rn(__fadd_rn(qq, pa.w), __fmul_rn(2.0f, dota));
                float dotb = fmaf(qz, pb.z, fmaf(qy, pb.y, __fmul_rn(qx, pb.x)));
                float d2b  = __fsub_rn(__fadd_rn(qq, pb.w), __fmul_rn(2.0f, dotb));
                bool pra = (ja < segE) && (d2a < R2F);
                bool prb = (jb < segE) && (d2b < R2F);
                unsigned ba = __ballot_sync(0xffffffffu, pra);
                unsigned bb = __ballot_sync(0xffffffffu, prb);

                int ia = __float_as_int(d2a);
                unsigned ua = (unsigned)ia ^ ((ia >= 0) ? 0x80000000u : 0xFFFFFFFFu);
                int posa = pra ? (count + __popc(ba & lmask)) : CANDMAX;
                posa = min(posa, CANDMAX);
                buf[w][posa] = make_uint2(ua, (unsigned)ja);

                int ca = __popc(ba);
                int ib = __float_as_int(d2b);
                unsigned ub = (unsigned)ib ^ ((ib >= 0) ? 0x80000000u : 0xFFFFFFFFu);
                int posb = prb ? (count + ca + __popc(bb & lmask)) : CANDMAX;
                posb = min(posb, CANDMAX);
                buf[w][posb] = make_uint2(ub, (unsigned)jb);

                count += ca + __popc(bb);   // uniform across the warp
            }
        }
    }
    __syncwarp();

    const int m = min(count, CANDMAX);

    // per-lane slots in named registers (no dynamic indexing)
    unsigned vd0, vd1, vd2, vd3, vp0, vp1, vp2, vp3;
    {
        uint2 e0 = (lane      < m) ? buf[w][lane]      : make_uint2(UINF, UINF);
        uint2 e1 = (lane + 32 < m) ? buf[w][lane + 32] : make_uint2(UINF, UINF);
        uint2 e2 = (lane + 64 < m) ? buf[w][lane + 64] : make_uint2(UINF, UINF);
        uint2 e3 = (lane + 96 < m) ? buf[w][lane + 96] : make_uint2(UINF, UINF);
        vd0 = e0.x; vp0 = e0.y;  vd1 = e1.x; vp1 = e1.y;
        vd2 = e2.x; vp2 = e2.y;  vd3 = e3.x; vp3 = e3.y;
    }

    // sort each lane's 4 slots ascending by (d2, pos): 5-CE network
    CE_(vd0, vp0, vd1, vp1); CE_(vd2, vp2, vd3, vp3);
    CE_(vd0, vp0, vd2, vp2); CE_(vd1, vp1, vd3, vp3);
    CE_(vd1, vp1, vd2, vp2);

    // top-10 by merging 32 sorted lane-lists: head is always (vd0, vp0)
    unsigned kd2 = UINF, kpos = 0u;
    #pragma unroll
    for (int i = 0; i < KNN; i++) {
        unsigned gmin = __reduce_min_sync(0xffffffffu, vd0);
        unsigned cnd  = (vd0 == gmin) ? vp0 : UINF;
        unsigned wpos = __reduce_min_sync(0xffffffffu, cnd);
        if (lane == i) { kd2 = gmin; kpos = wpos; }
        bool win = (vd0 == gmin) & (vp0 == wpos);
        vd0 = win ? vd1 : vd0;  vp0 = win ? vp1 : vp0;
        vd1 = win ? vd2 : vd1;  vp1 = win ? vp2 : vp1;
        vd2 = win ? vd3 : vd2;  vp2 = win ? vp3 : vp2;
        vd3 = win ? UINF : vd3;
    }

    // weights (per reference numerics)
    float wr = 0.0f;
    int nidx = 0;
    if (kd2 != UINF) {
        unsigned ub = kd2 ^ (((int)kd2 < 0) ? 0x80000000u : 0xFFFFFFFFu);
        float d2 = __int_as_float((int)ub);
        float dist = sqrtf(fmaxf(d2, 0.0f) + 1e-12f);
        if (dist < RADIUSF) wr = 1.0f / (dist + 1e-8f);
        nidx = g_sidx[kpos];               // only winner lanes load this
    }
    float ws = wr;
    #pragma unroll
    for (int off = 16; off; off >>= 1) ws += __shfl_xor_sync(0xffffffffu, ws, off);
    float wn = wr / (ws + 1e-8f);

    // weighted feature gather: each lane owns channels (2*lane, 2*lane+1)
    const float* fbase = feat + 2 * lane;
    float acc0 = 0.0f, acc1 = 0.0f;
    #pragma unroll
    for (int i = 0; i < KNN; i++) {
        float wi = __shfl_sync(0xffffffffu, wn, i);
        int ii = __shfl_sync(0xffffffffu, nidx, i);
        const float2 f2 = *reinterpret_cast<const float2*>(fbase + ii * CFEAT);
        acc0 = fmaf(wi, f2.x, acc0);
        acc1 = fmaf(wi, f2.y, acc1);
    }
    float* oq = out + q * OUTC;
    oq[2 * lane]     = acc0;
    oq[2 * lane + 1] = acc1;

    // positional encoding: oq[64..66]=xyz, oq[67+s]=sin, oq[91+s]=cos
    // s = oct*3 + d, a = coord_d * 2^oct  (matches reference flat order)
    if (lane < 24) {
        int oct = lane / 3;
        int d   = lane - oct * 3;
        float coord = (d == 0) ? qx : ((d == 1) ? qy : qz);
        float a = coord * (float)(1 << oct);
        oq[67 + lane] = __sinf(a);
        oq[91 + lane] = __cosf(a);
    } else if (lane < 27) {
        int d = lane - 24;
        oq[64 + d] = (d == 0) ? qx : ((d == 1) ? qy : qz);
    }
}

extern "C" void kernel_launch(void* const* d_in, const int* in_sizes, int n_in,
                              void* d_out, int out_size) {
    const float* xyz  = (const float*)d_in[0];   // [1, P, 3]
    const float* pcd  = (const float*)d_in[1];   // [1, N, 3]
    const float* feat = (const float*)d_in[2];   // [1, N, 64]
    float* out = (float*)d_out;                  // [1, P, 115]
    const int P = in_sizes[0] / 3;
    const int N = in_sizes[1] / 3;

    const int nb = (N + BTHR - 1) / BTHR;        // 64 blocks: fully resident
    build_kernel<<<nb, BTHR>>>(pcd, xyz, N, P);
    knn_kernel<<<(P + WPB - 1) / WPB, WPB * 32>>>(xyz, feat, out, P);
}

// round 17
// speedup vs baseline: 1.1778x; 1.1778x over previous
#include <cuda_runtime.h>
#include <cstdint>

// Problem constants (fixed by the dataset: B=1, P=8192, N=16384, C=64)
#define GRID_DIM 10
#define NCELLS   (GRID_DIM * GRID_DIM * GRID_DIM)
#define NPTS_MAX 16384
#define NQ_MAX   8192
#define CFEAT    64
#define OUTC     115          // 64 fcd + 3 xyz + 24 sin + 24 cos
#define KNN      10
#define R2F      0.01f
#define RADIUSF  0.1f
#define CANDMAX  128          // per-query candidate cap (E ~ 68.6, sigma ~ 8.3)
#define WPB      4            // warps (queries) per block
#define BTHR     256          // build threads per block
#define UINF     0xFFFFFFFFu

// ---- scratch: static __device__ arrays (no allocation allowed) ----
__device__ int    g_cntH[2][NCELLS];         // point histogram, ping-pong by parity
__device__ int    g_cntS[2][NCELLS];         // point scatter counters, ping-pong
__device__ int    g_qcntH[2][NCELLS];        // query histogram, ping-pong
__device__ int    g_qcntS[2][NCELLS];        // query scatter counters, ping-pong
__device__ int    g_entry;                   // monotonic across replays
__device__ int    g_done;                    // monotonic across replays
__device__ uint2  g_rows[NCELLS][9];         // per-cell neighbor row segments
__device__ float4 g_sorted[NPTS_MAX + 96];   // {x,y,z,|p|^2}; +96 zero pad
__device__ int    g_sidx[NPTS_MAX];          // original point index
__device__ int    g_qorder[NQ_MAX];          // queries sorted by cell

__device__ __forceinline__ int cell_coord(float v) {
    int c = (int)(v * 10.0f);
    return c < 0 ? 0 : (c > 9 ? 9 : c);
}
__device__ __forceinline__ int cell_of(float x, float y, float z) {
    return (cell_coord(z) * GRID_DIM + cell_coord(y)) * GRID_DIM + cell_coord(x);
}

// 256-thread exclusive scan of cnt[0..NCELLS) into s_out (incl. total at [NCELLS]).
__device__ __forceinline__ void scan1000(const int* __restrict__ cnt,
                                         int* __restrict__ s_out,
                                         int* __restrict__ warp_sums,
                                         int t) {
    const int lane = t & 31, wid = t >> 5;
    const int c0 = t * 4;
    int loc[4], pref = 0;
    #pragma unroll
    for (int r = 0; r < 4; r++) {
        int cc = c0 + r;
        int v = (cc < NCELLS) ? cnt[cc] : 0;
        loc[r] = pref; pref += v;
    }
    int inc = pref;
    #pragma unroll
    for (int off = 1; off < 32; off <<= 1) {
        int o = __shfl_up_sync(0xffffffffu, inc, off);
        if (lane >= off) inc += o;
    }
    if (lane == 31) warp_sums[wid] = inc;
    __syncthreads();
    if (wid == 0) {
        int v = (lane < BTHR / 32) ? warp_sums[lane] : 0;
        int s = v;
        #pragma unroll
        for (int off = 1; off < BTHR / 32; off <<= 1) {
            int o = __shfl_up_sync(0xffffffffu, s, off);
            if (lane >= off) s += o;
        }
        if (lane < BTHR / 32) warp_sums[lane] = s - v;
    }
    __syncthreads();
    const int base = warp_sums[wid] + (inc - pref);
    #pragma unroll
    for (int r = 0; r < 4; r++) {
        int cc = c0 + r;
        if (cc < NCELLS) s_out[cc] = base + loc[r];
    }
    if (t == BTHR - 1) s_out[NCELLS] = base + pref;   // total
}

// ---- build: count pts+queries -> poll-all -> 2x scan -> rows + scatter ----
__global__ void __launch_bounds__(BTHR)
build_kernel(const float* __restrict__ pcd, const float* __restrict__ xyz,
             int N, int P) {
    __shared__ int s_start[NCELLS + 1];
    __shared__ int s_qstart[NCELLS + 1];
    __shared__ int warp_sums[BTHR / 32];
    __shared__ int s_epoch;

    const int t   = threadIdx.x;
    const int bid = blockIdx.x;
    const int nb  = gridDim.x;
    const int i   = bid * BTHR + t;

    if (t == 0) s_epoch = atomicAdd(&g_entry, 1) / nb;
    __syncthreads();
    const int E = s_epoch;
    const int p = E & 1;

    // ---- count points ----
    float x = 0.f, y = 0.f, z = 0.f, pp = 0.f;
    int c = 0;
    const bool valid = (i < N);
    if (valid) {
        x = pcd[3 * i]; y = pcd[3 * i + 1]; z = pcd[3 * i + 2];
        pp = __fadd_rn(__fadd_rn(__fmul_rn(x, x), __fmul_rn(y, y)),
                       __fmul_rn(z, z));            // |p|^2 as reference
        c = cell_of(x, y, z);
        atomicAdd(&g_cntH[p][c], 1);
    }
    // ---- count queries ----
    int qc = 0;
    const bool qvalid = (i < P);
    if (qvalid) {
        float qx = xyz[3 * i], qy = xyz[3 * i + 1], qz = xyz[3 * i + 2];
        qc = cell_of(qx, qy, qz);
        atomicAdd(&g_qcntH[p][qc], 1);
    }
    __threadfence();
    __syncthreads();
    if (t == 0) {
        atomicAdd(&g_done, 1);
        while (*((volatile int*)&g_done) < (E + 1) * nb) __nanosleep(32);
    }
    __syncthreads();
    __threadfence();

    // ---- redundant parallel scans into smem (identical in every block) ----
    scan1000(g_cntH[p], s_start, warp_sums, t);
    __syncthreads();
    scan1000(g_qcntH[p], s_qstart, warp_sums, t);
    __syncthreads();

    // ---- per-cell neighbor-row table (1000 threads across the grid) ----
    // Block b owns cells [b*16, b*16+16) to spread the work.
    {
        int cc = bid * 16 + t;
        if (t < 16 && cc < NCELLS) {
            int cx = cc % GRID_DIM;
            int cy = (cc / GRID_DIM) % GRID_DIM;
            int cz = cc / (GRID_DIM * GRID_DIM);
            int x0 = max(cx - 1, 0), x1 = min(cx + 1, GRID_DIM - 1);
            #pragma unroll
            for (int r = 0; r < 9; r++) {
                int yy = cy - 1 + (r % 3);
                int zz = cz - 1 + (r / 3);
                uint2 seg = make_uint2(0u, 0u);
                if (yy >= 0 && yy < GRID_DIM && zz >= 0 && zz < GRID_DIM) {
                    int cbase = (zz * GRID_DIM + yy) * GRID_DIM;
                    seg.x = (unsigned)s_start[cbase + x0];
                    seg.y = (unsigned)s_start[cbase + x1 + 1];
                }
                g_rows[cc][r] = seg;
            }
        }
    }

    // ---- scatter points ----
    if (valid) {
        int pos = s_start[c] + atomicAdd(&g_cntS[p][c], 1);
        g_sorted[pos] = make_float4(x, y, z, pp);
        g_sidx[pos] = i;
    }
    // ---- scatter queries (cell-sorted order for knn locality) ----
    if (qvalid) {
        int pos = s_qstart[qc] + atomicAdd(&g_qcntS[p][qc], 1);
        g_qorder[pos] = i;
    }

    // ---- zero the other parity for the next epoch ----
    if (i < NCELLS) {
        g_cntH[1 - p][i] = 0;
        g_cntS[1 - p][i] = 0;
        g_qcntH[1 - p][i] = 0;
        g_qcntS[1 - p][i] = 0;
    }
}

// compare-exchange on (d2,pos) pairs, ascending
#define CE_(da,pa,db,pb) { \
    bool sw_ = (da > db) || ((da == db) && (pa > pb)); \
    unsigned td_ = sw_ ? db : da, tp_ = sw_ ? pb : pa; \
    db = sw_ ? da : db; pb = sw_ ? pa : pb; da = td_; pa = tp_; }

// ---- main: warp-per-query radius KNN + aggregate + positional encoding ----
__global__ void __launch_bounds__(WPB * 32)
knn_kernel(const float* __restrict__ xyz,
           const float* __restrict__ feat,
           float* __restrict__ out, int P) {
    __shared__ uint2 buf[WPB][CANDMAX + 1];    // +1: slot 128 is the trash slot

    const int w    = threadIdx.x >> 5;
    const int lane = threadIdx.x & 31;
    const int gid  = blockIdx.x * WPB + w;
    if (gid >= P) return;                  // warp-uniform
    const int q = g_qorder[gid];           // cell-sorted query order

    const float qx = xyz[3 * q], qy = xyz[3 * q + 1], qz = xyz[3 * q + 2];
    const float qq = __fadd_rn(__fadd_rn(__fmul_rn(qx, qx), __fmul_rn(qy, qy)),
                               __fmul_rn(qz, qz));

    const int qcell = cell_of(qx, qy, qz);
    const uint2* __restrict__ rows = g_rows[qcell];

    int count = 0;                          // warp-uniform candidate count
    const unsigned lmask = (1u << lane) - 1u;
    #pragma unroll 1
    for (int r = 0; r < 9; r++) {
        const uint2 seg = rows[r];          // table is L1-hot (block shares cell)
        const int segS = (int)seg.x;
        const int segE = (int)seg.y;
        // 64 points per iteration: 2 per lane, 2 independent LDG.128s.
        // Stores are BRANCHLESS: failing/overflow lanes write trash slot.
        for (int j0 = segS; j0 < segE; j0 += 64) {
            const int ja = j0 + lane;
            const int jb = ja + 32;
            float4 pa = g_sorted[ja];       // padded array: always safe
            float4 pb = g_sorted[jb];
            float dota = fmaf(qz, pa.z, fmaf(qy, pa.y, __fmul_rn(qx, pa.x)));
            float d2a  = __fsub_rn(__fadd_rn(qq, pa.w), __fmul_rn(2.0f, dota));
            float dotb = fmaf(qz, pb.z, fmaf(qy, pb.y, __fmul_rn(qx, pb.x)));
            float d2b  = __fsub_rn(__fadd_rn(qq, pb.w), __fmul_rn(2.0f, dotb));
            bool pra = (ja < segE) && (d2a < R2F);
            bool prb = (jb < segE) && (d2b < R2F);
            unsigned ba = __ballot_sync(0xffffffffu, pra);
            unsigned bb = __ballot_sync(0xffffffffu, prb);

            int ia = __float_as_int(d2a);
            unsigned ua = (unsigned)ia ^ ((ia >= 0) ? 0x80000000u : 0xFFFFFFFFu);
            int posa = pra ? (count + __popc(ba & lmask)) : CANDMAX;
            posa = min(posa, CANDMAX);
            buf[w][posa] = make_uint2(ua, (unsigned)ja);

            int ca = __popc(ba);
            int ib = __float_as_int(d2b);
            unsigned ub = (unsigned)ib ^ ((ib >= 0) ? 0x80000000u : 0xFFFFFFFFu);
            int posb = prb ? (count + ca + __popc(bb & lmask)) : CANDMAX;
            posb = min(posb, CANDMAX);
            buf[w][posb] = make_uint2(ub, (unsigned)jb);

            count += ca + __popc(bb);       // uniform across the warp
        }
    }
    __syncwarp();

    const int m = min(count, CANDMAX);

    // per-lane slots in named registers (no dynamic indexing)
    unsigned vd0, vd1, vd2, vd3, vp0, vp1, vp2, vp3;
    {
        uint2 e0 = (lane      < m) ? buf[w][lane]      : make_uint2(UINF, UINF);
        uint2 e1 = (lane + 32 < m) ? buf[w][lane + 32] : make_uint2(UINF, UINF);
        uint2 e2 = (lane + 64 < m) ? buf[w][lane + 64] : make_uint2(UINF, UINF);
        uint2 e3 = (lane + 96 < m) ? buf[w][lane + 96] : make_uint2(UINF, UINF);
        vd0 = e0.x; vp0 = e0.y;  vd1 = e1.x; vp1 = e1.y;
        vd2 = e2.x; vp2 = e2.y;  vd3 = e3.x; vp3 = e3.y;
    }

    // sort each lane's 4 slots ascending by (d2, pos): 5-CE network
    CE_(vd0, vp0, vd1, vp1); CE_(vd2, vp2, vd3, vp3);
    CE_(vd0, vp0, vd2, vp2); CE_(vd1, vp1, vd3, vp3);
    CE_(vd1, vp1, vd2, vp2);

    // top-10 by merging 32 sorted lane-lists: head is always (vd0, vp0)
    unsigned kd2 = UINF, kpos = 0u;
    #pragma unroll
    for (int i = 0; i < KNN; i++) {
        unsigned gmin = __reduce_min_sync(0xffffffffu, vd0);
        unsigned cnd  = (vd0 == gmin) ? vp0 : UINF;
        unsigned wpos = __reduce_min_sync(0xffffffffu, cnd);
        if (lane == i) { kd2 = gmin; kpos = wpos; }
        bool win = (vd0 == gmin) & (vp0 == wpos);
        vd0 = win ? vd1 : vd0;  vp0 = win ? vp1 : vp0;
        vd1 = win ? vd2 : vd1;  vp1 = win ? vp2 : vp1;
        vd2 = win ? vd3 : vd2;  vp2 = win ? vp3 : vp2;
        vd3 = win ? UINF : vd3;
    }

    // weights (per reference numerics)
    float wr = 0.0f;
    int nidx = 0;
    if (kd2 != UINF) {
        unsigned ub = kd2 ^ (((int)kd2 < 0) ? 0x80000000u : 0xFFFFFFFFu);
        float d2 = __int_as_float((int)ub);
        float dist = sqrtf(fmaxf(d2, 0.0f) + 1e-12f);
        if (dist < RADIUSF) wr = 1.0f / (dist + 1e-8f);
        nidx = g_sidx[kpos];               // only winner lanes load this
    }
    float ws = wr;
    #pragma unroll
    for (int off = 16; off; off >>= 1) ws += __shfl_xor_sync(0xffffffffu, ws, off);
    float wn = wr / (ws + 1e-8f);

    // weighted feature gather: each lane owns channels (2*lane, 2*lane+1)
    const float* fbase = feat + 2 * lane;
    float acc0 = 0.0f, acc1 = 0.0f;
    #pragma unroll
    for (int i = 0; i < KNN; i++) {
        float wi = __shfl_sync(0xffffffffu, wn, i);
        int ii = __shfl_sync(0xffffffffu, nidx, i);
        const float2 f2 = *reinterpret_cast<const float2*>(fbase + ii * CFEAT);
        acc0 = fmaf(wi, f2.x, acc0);
        acc1 = fmaf(wi, f2.y, acc1);
    }
    float* oq = out + q * OUTC;
    oq[2 * lane]     = acc0;
    oq[2 * lane + 1] = acc1;

    // positional encoding: oq[64..66]=xyz, oq[67+s]=sin, oq[91+s]=cos
    // s = oct*3 + d, a = coord_d * 2^oct  (matches reference flat order)
    if (lane < 24) {
        int oct = lane / 3;
        int d   = lane - oct * 3;
        float coord = (d == 0) ? qx : ((d == 1) ? qy : qz);
        float a = coord * (float)(1 << oct);
        oq[67 + lane] = __sinf(a);
        oq[91 + lane] = __cosf(a);
    } else if (lane < 27) {
        int d = lane - 24;
        oq[64 + d] = (d == 0) ? qx : ((d == 1) ? qy : qz);
    }
}

extern "C" void kernel_launch(void* const* d_in, const int* in_sizes, int n_in,
                              void* d_out, int out_size) {
    const float* xyz  = (const float*)d_in[0];   // [1, P, 3]
    const float* pcd  = (const float*)d_in[1];   // [1, N, 3]
    const float* feat = (const float*)d_in[2];   // [1, N, 64]
    float* out = (float*)d_out;                  // [1, P, 115]
    const int P = in_sizes[0] / 3;
    const int N = in_sizes[1] / 3;

    const int nb = (N + BTHR - 1) / BTHR;        // 64 blocks: fully resident
    build_kernel<<<nb, BTHR>>>(pcd, xyz, N, P);
    knn_kernel<<<(P + WPB - 1) / WPB, WPB * 32>>>(xyz, feat, out, P);
}